// round 3
// baseline (speedup 1.0000x reference)
#include <cuda_runtime.h>
#include <cstdint>
#include <cstddef>

// ============================================================================
// ModConv2D on GB300 (sm_103 base target — tcgen05 unavailable in this
// toolchain), tf32 mma.sync implicit-GEMM conv.
//
//   y = conv2d_3x3_same(x * s_b[ci], kernel) * invn_b[co]
//   s_b[ci]    = style[b,ci] + 1
//   invn_b[co] = 1/sqrt( sum_{kh,kw,ci} (kernel*s_b)^2 + 1e-8 )
// ============================================================================

constexpr int BATCH = 16, HH = 64, WWD = 64, CIN = 256, CO = 256;

#define DEVINL __device__ __forceinline__

// scratch (allocation-free rule: __device__ globals)
__device__ float g_Wt[9 * CO * CIN];              // [tap][co][ci], tf32 bits
__device__ float g_invn[BATCH * CO];              // demodulation scale
__device__ float g_xs[BATCH * HH * WWD * CIN];    // style-scaled x, tf32 bits

DEVINL uint32_t smem_u32(const void* p) {
    uint32_t a;
    asm("{ .reg .u64 t; cvta.to.shared.u64 t, %1; cvt.u32.u64 %0, t; }"
        : "=r"(a) : "l"(p));
    return a;
}
DEVINL uint32_t f2tf(float f) {
    uint32_t r;
    asm("cvt.rna.tf32.f32 %0, %1;" : "=r"(r) : "f"(f));
    return r;
}
DEVINL void cp16(uint32_t dst, const void* src, uint32_t sz) {
    asm volatile("cp.async.cg.shared.global [%0], [%1], 16, %2;"
                 :: "r"(dst), "l"(src), "r"(sz) : "memory");
}
DEVINL void cp_commit() {
    asm volatile("cp.async.commit_group;" ::: "memory");
}
template <int N> DEVINL void cp_wait() {
    asm volatile("cp.async.wait_group %0;" :: "n"(N) : "memory");
}

// m16n8k8 tf32 MMA (row-major A, col-major B, fp32 accum)
DEVINL void mma8(float* d, const uint32_t* a, uint32_t b0, uint32_t b1) {
    asm volatile(
        "mma.sync.aligned.m16n8k8.row.col.f32.tf32.tf32.f32 "
        "{%0,%1,%2,%3}, {%4,%5,%6,%7}, {%8,%9}, {%0,%1,%2,%3};"
        : "+f"(d[0]), "+f"(d[1]), "+f"(d[2]), "+f"(d[3])
        : "r"(a[0]), "r"(a[1]), "r"(a[2]), "r"(a[3]), "r"(b0), "r"(b1));
}

// ------------- smem layout -------------
// 4 stages x (A: 128x32 f32 = 16KB, B: 256x32 f32 = 32KB) = 192KB, + invn 1KB
constexpr uint32_t STAGE_BYTES = 49152;
constexpr uint32_t SMEM_BYTES  = 4 * STAGE_BYTES + 1024;

// ============================================================================
// Prolog 1: weights -> g_Wt[tap][co][ci], tf32-converted (transpose)
// ============================================================================
__global__ void prep_wt(const float* __restrict__ ker) {
    __shared__ float t[32][33];
    const int tap = blockIdx.z, ci0 = blockIdx.y * 32, co0 = blockIdx.x * 32;
    const int tx = threadIdx.x, ty = threadIdx.y;   // (32, 8)
    #pragma unroll
    for (int i = 0; i < 32; i += 8)
        t[ty + i][tx] = ker[((tap * 256) + (ci0 + ty + i)) * 256 + co0 + tx];
    __syncthreads();
    #pragma unroll
    for (int i = 0; i < 32; i += 8) {
        float v = t[tx][ty + i];
        reinterpret_cast<uint32_t*>(g_Wt)[((tap * 256) + (co0 + ty + i)) * 256 + ci0 + tx] =
            f2tf(v);
    }
}

// ============================================================================
// Prolog 2: demodulation scales invn[b][co] (fp32)
// ============================================================================
__global__ void prep_norm(const float* __restrict__ ker, const float* __restrict__ style) {
    __shared__ float s2[256];
    const int b = blockIdx.x, co = threadIdx.x;
    float s = style[b * 256 + co] + 1.0f;
    s2[co] = s * s;
    __syncthreads();
    float acc = 0.0f;
    for (int t9 = 0; t9 < 9; ++t9) {
        const float* kp = ker + t9 * 256 * 256 + co;
        #pragma unroll 4
        for (int ci = 0; ci < 256; ++ci) {
            float v = kp[ci * 256];
            acc = fmaf(v * v, s2[ci], acc);
        }
    }
    float a = acc + 1e-8f;
    float r = rsqrtf(a);
    r = r * (1.5f - 0.5f * a * r * r);   // Newton step
    g_invn[b * 256 + co] = r;
}

// ============================================================================
// Prolog 3: xs = tf32(x * (style+1)), NHWC layout preserved
// ============================================================================
__global__ void prep_x(const float* __restrict__ x, const float* __restrict__ style) {
    __shared__ float s[256];
    const size_t i = (size_t)blockIdx.x * 256 + threadIdx.x;  // over 4M float4
    const int b = (int)(i >> 18);                             // 2^18 float4 per sample
    s[threadIdx.x] = style[b * 256 + threadIdx.x] + 1.0f;
    __syncthreads();
    float4 v = reinterpret_cast<const float4*>(x)[i];
    const int ci = ((int)i & 63) * 4;
    uint4 o;
    o.x = f2tf(v.x * s[ci + 0]);
    o.y = f2tf(v.y * s[ci + 1]);
    o.z = f2tf(v.z * s[ci + 2]);
    o.w = f2tf(v.w * s[ci + 3]);
    reinterpret_cast<uint4*>(g_xs)[i] = o;
}

// ============================================================================
// Main GEMM: 512 CTAs, each 128 pixels x 256 cout, K = 72 chunks of 32.
// 4-stage cp.async pipeline; warp tile 32x128 via m16n8k8 tf32 mma.sync.
//
// smem element (row r, ci c): word = r*32 + ((c>>2) ^ (r&7))*4 + (c&3)
// -> conflict-free fragment LDS for all a0..a3 / b0,b1 lane patterns.
// ============================================================================
__global__ void __launch_bounds__(256, 1)
modconv_main(float* __restrict__ out) {
    extern __shared__ char smem[];
    const uint32_t sb = smem_u32(smem);
    const int tid = threadIdx.x, lid = tid & 31, wid = tid >> 5;
    const int g = lid >> 2, tg = lid & 3;
    const int wm = wid & 3, wn = wid >> 2;
    const int M0 = wm * 32, N0 = wn * 128;
    const int tile = blockIdx.x;
    const int b = tile >> 5;             // 32 tiles (of 128 pixels) per sample
    const int h0 = (tile & 31) * 2;      // 2 image rows per tile

    float acc[2][16][4];
    #pragma unroll
    for (int mt = 0; mt < 2; ++mt)
        #pragma unroll
        for (int nt = 0; nt < 16; ++nt)
            #pragma unroll
            for (int i = 0; i < 4; ++i) acc[mt][nt][i] = 0.0f;

    auto load_stage = [&](int slot, int it) {
        const int tap = it >> 3, ci0 = (it & 7) * 32;
        const int dh = tap / 3 - 1, dw = tap % 3 - 1;
        const uint32_t abase = sb + (uint32_t)slot * STAGE_BYTES;
        const uint32_t bbase = abase + 16384u;
        #pragma unroll
        for (int j = 0; j < 4; ++j) {                 // A: 128 rows x 32 ci
            const int q = tid + j * 256;
            const int m = q >> 3, c4 = q & 7;
            const int h = h0 + (m >> 6) + dh;
            const int w = (m & 63) + dw;
            const bool ok = ((unsigned)h < 64u) & ((unsigned)w < 64u);
            const float* src = ok
                ? g_xs + (((size_t)((b * 64 + h) * 64 + w)) * 256 + ci0 + c4 * 4)
                : g_xs;
            cp16(abase + (uint32_t)(m * 128 + ((c4 ^ (m & 7)) << 4)), src, ok ? 16u : 0u);
        }
        #pragma unroll
        for (int j = 0; j < 8; ++j) {                 // B: 256 co x 32 ci
            const int q = tid + j * 256;
            const int co = q >> 3, c4 = q & 7;
            const float* src = g_Wt + ((size_t)(tap * 256 + co) * 256 + ci0 + c4 * 4);
            cp16(bbase + (uint32_t)(co * 128 + ((c4 ^ (co & 7)) << 4)), src, 16u);
        }
    };

    load_stage(0, 0); cp_commit();
    load_stage(1, 1); cp_commit();
    load_stage(2, 2); cp_commit();

    const int ra = (M0 + g) * 32 + tg;    // A word base (row M0+g), (row&7)==g
    const int rb = (N0 + g) * 32 + tg;    // B word base (co  N0+g), (co&7)==g

    #pragma unroll 1
    for (int it = 0; it < 72; ++it) {
        cp_wait<2>();
        __syncthreads();
        if (it + 3 < 72) load_stage((it + 3) & 3, it + 3);
        cp_commit();

        const uint32_t* As =
            reinterpret_cast<const uint32_t*>(smem + (size_t)(it & 3) * STAGE_BYTES);
        const uint32_t* Bs = As + 4096;

        #pragma unroll
        for (int ks = 0; ks < 4; ++ks) {
            const int sw0 = ((2 * ks) ^ g) * 4;
            const int sw1 = ((2 * ks + 1) ^ g) * 4;
            uint32_t a[2][4];
            #pragma unroll
            for (int mt = 0; mt < 2; ++mt) {
                const int base = ra + mt * 512;
                a[mt][0] = As[base + sw0];
                a[mt][1] = As[base + 256 + sw0];
                a[mt][2] = As[base + sw1];
                a[mt][3] = As[base + 256 + sw1];
            }
            #pragma unroll
            for (int nt = 0; nt < 16; ++nt) {
                const uint32_t b0 = Bs[rb + nt * 256 + sw0];
                const uint32_t b1 = Bs[rb + nt * 256 + sw1];
                mma8(acc[0][nt], a[0], b0, b1);
                mma8(acc[1][nt], a[1], b0, b1);
            }
        }
    }

    // ---- epilogue: demodulate + store ----
    float* invn_sm = reinterpret_cast<float*>(smem + 4 * STAGE_BYTES);
    __syncthreads();
    invn_sm[tid] = g_invn[b * 256 + tid];
    __syncthreads();

    #pragma unroll
    for (int mt = 0; mt < 2; ++mt) {
        const int m = tile * 128 + M0 + mt * 16 + g;
        float* o0 = out + (size_t)m * 256;
        float* o1 = out + (size_t)(m + 8) * 256;
        #pragma unroll
        for (int nt = 0; nt < 16; ++nt) {
            const int co = N0 + nt * 8 + tg * 2;
            const float s0 = invn_sm[co], s1 = invn_sm[co + 1];
            float2 v0 = make_float2(acc[mt][nt][0] * s0, acc[mt][nt][1] * s1);
            float2 v1 = make_float2(acc[mt][nt][2] * s0, acc[mt][nt][3] * s1);
            *reinterpret_cast<float2*>(o0 + co) = v0;
            *reinterpret_cast<float2*>(o1 + co) = v1;
        }
    }
}

// ============================================================================
// Host launcher
// ============================================================================
extern "C" void kernel_launch(void* const* d_in, const int* in_sizes, int n_in,
                              void* d_out, int out_size) {
    const float* x  = (const float*)d_in[0];
    const float* st = (n_in > 1) ? (const float*)d_in[1] : nullptr;
    const float* kr = (n_in > 2) ? (const float*)d_in[2] : nullptr;
    for (int i = 0; i < n_in; ++i) {
        if (in_sizes[i] == BATCH * HH * WWD * CIN) x  = (const float*)d_in[i];
        else if (in_sizes[i] == BATCH * CIN)       st = (const float*)d_in[i];
        else if (in_sizes[i] == 9 * CIN * CO)      kr = (const float*)d_in[i];
    }
    float* out = (float*)d_out;

    cudaFuncSetAttribute(modconv_main, cudaFuncAttributeMaxDynamicSharedMemorySize,
                         (int)SMEM_BYTES);

    prep_wt<<<dim3(8, 8, 9), dim3(32, 8)>>>(kr);
    prep_norm<<<16, 256>>>(kr, st);
    prep_x<<<16384, 256>>>(x, st);
    modconv_main<<<512, 256, SMEM_BYTES>>>(out);
}

// round 4
// speedup vs baseline: 1.8599x; 1.8599x over previous
#include <cuda_runtime.h>
#include <cuda_fp16.h>
#include <cstdint>
#include <cstddef>

// ============================================================================
// ModConv2D on GB300 (sm_103 base target), fp16 mma.sync implicit-GEMM conv.
//
//   y = conv2d_3x3_same(x * s_b[ci], kernel) * invn_b[co]
//   s_b[ci]    = style[b,ci] + 1
//   invn_b[co] = 1/sqrt( sum_{kh,kw,ci} (kernel*s_b)^2 + 1e-8 )
//
// fp16 has the same 10-bit mantissa as tf32; products are exact in fp32 and
// accumulation is fp32, so accuracy matches the tf32 version (~3e-4) while
// the legacy HMMA fp16 path runs at 2x the tf32 MAC rate.
// ============================================================================

constexpr int BATCH = 16, HH = 64, WWD = 64, CIN = 256, CO = 256;

#define DEVINL __device__ __forceinline__

// scratch (allocation-free rule: __device__ globals)
__device__ __half g_Wh[9 * CO * CIN];             // [tap][co][ci], fp16
__device__ __half g_xh[BATCH * HH * WWD * CIN];   // style-scaled x, fp16
__device__ float  g_K2[CIN * CO];                 // sum_tap k^2
__device__ float  g_invn[BATCH * CO];             // demodulation scale

DEVINL uint32_t smem_u32(const void* p) {
    uint32_t a;
    asm("{ .reg .u64 t; cvta.to.shared.u64 t, %1; cvt.u32.u64 %0, t; }"
        : "=r"(a) : "l"(p));
    return a;
}
DEVINL void cp16(uint32_t dst, const void* src, uint32_t sz) {
    asm volatile("cp.async.cg.shared.global [%0], [%1], 16, %2;"
                 :: "r"(dst), "l"(src), "r"(sz) : "memory");
}
DEVINL void cp_commit() { asm volatile("cp.async.commit_group;" ::: "memory"); }
template <int N> DEVINL void cp_wait() {
    asm volatile("cp.async.wait_group %0;" :: "n"(N) : "memory");
}
DEVINL void ldsm4(uint32_t* r, uint32_t addr) {
    asm volatile("ldmatrix.sync.aligned.m8n8.x4.shared.b16 {%0,%1,%2,%3}, [%4];"
                 : "=r"(r[0]), "=r"(r[1]), "=r"(r[2]), "=r"(r[3]) : "r"(addr));
}
// m16n8k16 fp16 MMA (row-major A, col-major B, fp32 accum)
DEVINL void mma16(float* d, const uint32_t* a, uint32_t b0, uint32_t b1) {
    asm volatile(
        "mma.sync.aligned.m16n8k16.row.col.f32.f16.f16.f32 "
        "{%0,%1,%2,%3}, {%4,%5,%6,%7}, {%8,%9}, {%0,%1,%2,%3};"
        : "+f"(d[0]), "+f"(d[1]), "+f"(d[2]), "+f"(d[3])
        : "r"(a[0]), "r"(a[1]), "r"(a[2]), "r"(a[3]), "r"(b0), "r"(b1));
}

// ------------- smem layout -------------
// stage: A 128x32 half (8KB) + B 256x32 half (16KB) = 24KB; 4 stages + invn.
// Element (row r, ci-chunk c of 8 halves): byte = r*64 + ((c ^ ((r>>1)&3))*16)
// -> conflict-free for both cp.async row stores and ldmatrix 8-row reads.
constexpr uint32_t STAGE_BYTES = 24576;
constexpr uint32_t B_OFF       = 8192;
constexpr uint32_t SMEM_BYTES  = 4 * STAGE_BYTES + 1024;

// ============================================================================
// Prolog 1: weights -> g_Wh[tap][co][ci] (transpose + fp16)
// ============================================================================
__global__ void prep_wt(const float* __restrict__ ker) {
    __shared__ float t[32][33];
    const int tap = blockIdx.z, ci0 = blockIdx.y * 32, co0 = blockIdx.x * 32;
    const int tx = threadIdx.x, ty = threadIdx.y;   // (32, 8)
    #pragma unroll
    for (int i = 0; i < 32; i += 8)
        t[ty + i][tx] = ker[((tap * 256) + (ci0 + ty + i)) * 256 + co0 + tx];
    __syncthreads();
    #pragma unroll
    for (int i = 0; i < 32; i += 8)
        g_Wh[((tap * 256) + (co0 + ty + i)) * 256 + ci0 + tx] =
            __float2half_rn(t[tx][ty + i]);
}

// ============================================================================
// Prolog 2a: K2[ci][co] = sum_tap ker^2 (wide: 256 CTAs, coalesced over co)
// ============================================================================
__global__ void prep_k2(const float* __restrict__ ker) {
    const int ci = blockIdx.x, co = threadIdx.x;
    float a = 0.0f;
    #pragma unroll
    for (int t = 0; t < 9; ++t) {
        float v = ker[((size_t)t * 256 + ci) * 256 + co];
        a = fmaf(v, v, a);
    }
    g_K2[ci * 256 + co] = a;
}

// ============================================================================
// Prolog 2b: invn[b][co] = rsqrt( sum_ci K2[ci][co]*s^2 + 1e-8 )
// ============================================================================
__global__ void prep_norm(const float* __restrict__ style) {
    __shared__ float s2[256];
    const int b = blockIdx.x, co = threadIdx.x;
    float s = style[b * 256 + co] + 1.0f;
    s2[co] = s * s;
    __syncthreads();
    float acc = 0.0f;
    #pragma unroll 8
    for (int ci = 0; ci < 256; ++ci)
        acc = fmaf(g_K2[ci * 256 + co], s2[ci], acc);
    float a = acc + 1e-8f;
    float r = rsqrtf(a);
    r = r * (1.5f - 0.5f * a * r * r);   // Newton step
    g_invn[b * 256 + co] = r;
}

// ============================================================================
// Prolog 3: xh = fp16(x * (style+1)), NHWC layout preserved
// ============================================================================
__global__ void prep_x(const float* __restrict__ x, const float* __restrict__ style) {
    __shared__ float s[256];
    const size_t i = (size_t)blockIdx.x * 256 + threadIdx.x;  // over 4M float4
    const int b = (int)(i >> 18);
    s[threadIdx.x] = style[b * 256 + threadIdx.x] + 1.0f;
    __syncthreads();
    float4 v = reinterpret_cast<const float4*>(x)[i];
    const int ci = ((int)i & 63) * 4;
    __half2 h0 = __floats2half2_rn(v.x * s[ci + 0], v.y * s[ci + 1]);
    __half2 h1 = __floats2half2_rn(v.z * s[ci + 2], v.w * s[ci + 3]);
    uint2 o;
    o.x = *reinterpret_cast<uint32_t*>(&h0);
    o.y = *reinterpret_cast<uint32_t*>(&h1);
    reinterpret_cast<uint2*>(g_xh)[i] = o;
}

// ============================================================================
// Main GEMM: 512 CTAs x 256 thr, CTA tile 128 pixels x 256 cout,
// K = 72 chunks of 32 ci (9 taps x 8). 4-stage cp.async pipeline,
// ldmatrix.x4 fragment loads, m16n8k16 fp16 mma, fp32 accum.
// Warp tile 32x128 (4 m-warps x 2 n-warps).
// ============================================================================
__global__ void __launch_bounds__(256, 1)
modconv_main(float* __restrict__ out) {
    extern __shared__ char smem[];
    const uint32_t sb = smem_u32(smem);
    const int tid = threadIdx.x, lid = tid & 31, wid = tid >> 5;
    const int g = lid >> 2, tg = lid & 3;
    const int wm = wid & 3, wn = wid >> 2;
    const int M0 = wm * 32, N0 = wn * 128;
    const int tile = blockIdx.x;
    const int b = tile >> 5;             // 32 tiles (of 128 pixels) per sample
    const int h0 = (tile & 31) * 2;      // 2 image rows per tile

    float acc[2][16][4];
    #pragma unroll
    for (int mt = 0; mt < 2; ++mt)
        #pragma unroll
        for (int nt = 0; nt < 16; ++nt)
            #pragma unroll
            for (int i = 0; i < 4; ++i) acc[mt][nt][i] = 0.0f;

    // per-lane ldmatrix base offsets (stage-relative), ks=0
    const int la = lid & 7;
    uint32_t offA, offB;
    {
        const int rA = M0 + la + ((lid >> 3) & 1) * 8;
        const int cA = (lid >> 4) & 1;
        offA = (uint32_t)(rA * 64 + ((cA ^ ((rA >> 1) & 3)) << 4));
        const int rB = N0 + la + ((lid >> 4) & 1) * 8;
        const int cB = (lid >> 3) & 1;
        offB = B_OFF + (uint32_t)(rB * 64 + ((cB ^ ((rB >> 1) & 3)) << 4));
    }

    auto load_stage = [&](int slot, int it) {
        const int tap = it >> 3, ci0 = (it & 7) * 32;
        const int dh = tap / 3 - 1, dw = tap % 3 - 1;
        const uint32_t abase = sb + (uint32_t)slot * STAGE_BYTES;
        const uint32_t bbase = abase + B_OFF;
        // A: 128 rows x 4 chunks of 8 halves (16B) = 512 chunks, 2/thread
        #pragma unroll
        for (int j = 0; j < 2; ++j) {
            const int q = tid + j * 256;
            const int m = q >> 2, c = q & 3;
            const int h = h0 + (m >> 6) + dh;
            const int w = (m & 63) + dw;
            const bool ok = ((unsigned)h < 64u) & ((unsigned)w < 64u);
            const __half* src = ok
                ? g_xh + (((size_t)((b * 64 + h) * 64 + w)) * 256 + ci0 + c * 8)
                : g_xh;
            cp16(abase + (uint32_t)(m * 64 + ((c ^ ((m >> 1) & 3)) << 4)),
                 src, ok ? 16u : 0u);
        }
        // B: 256 co rows x 4 chunks = 1024 chunks, 4/thread
        #pragma unroll
        for (int j = 0; j < 4; ++j) {
            const int q = tid + j * 256;
            const int co = q >> 2, c = q & 3;
            const __half* src = g_Wh + ((size_t)(tap * 256 + co) * 256 + ci0 + c * 8);
            cp16(bbase + (uint32_t)(co * 64 + ((c ^ ((co >> 1) & 3)) << 4)), src, 16u);
        }
    };

    load_stage(0, 0); cp_commit();
    load_stage(1, 1); cp_commit();
    load_stage(2, 2); cp_commit();

    #pragma unroll 1
    for (int it = 0; it < 72; ++it) {
        cp_wait<2>();
        __syncthreads();
        if (it + 3 < 72) load_stage((it + 3) & 3, it + 3);
        cp_commit();

        const uint32_t stb = sb + (uint32_t)(it & 3) * STAGE_BYTES;
        #pragma unroll
        for (int ks = 0; ks < 2; ++ks) {
            const uint32_t kx = (uint32_t)ks << 5;   // chunk pair -> XOR 32
            uint32_t a[2][4];
            ldsm4(a[0], stb + (offA ^ kx));
            ldsm4(a[1], stb + 1024 + (offA ^ kx));
            #pragma unroll
            for (int j = 0; j < 8; ++j) {
                uint32_t bf[4];
                ldsm4(bf, stb + j * 1024 + (offB ^ kx));
                mma16(acc[0][2 * j],     a[0], bf[0], bf[1]);
                mma16(acc[1][2 * j],     a[1], bf[0], bf[1]);
                mma16(acc[0][2 * j + 1], a[0], bf[2], bf[3]);
                mma16(acc[1][2 * j + 1], a[1], bf[2], bf[3]);
            }
        }
    }

    // ---- epilogue: demodulate + store ----
    float* invn_sm = reinterpret_cast<float*>(smem + 4 * STAGE_BYTES);
    __syncthreads();
    invn_sm[tid] = g_invn[b * 256 + tid];
    __syncthreads();

    #pragma unroll
    for (int mt = 0; mt < 2; ++mt) {
        const int m = tile * 128 + M0 + mt * 16 + g;
        float* o0 = out + (size_t)m * 256;
        float* o1 = out + (size_t)(m + 8) * 256;
        #pragma unroll
        for (int nt = 0; nt < 16; ++nt) {
            const int co = N0 + nt * 8 + tg * 2;
            const float s0 = invn_sm[co], s1 = invn_sm[co + 1];
            float2 v0 = make_float2(acc[mt][nt][0] * s0, acc[mt][nt][1] * s1);
            float2 v1 = make_float2(acc[mt][nt][2] * s0, acc[mt][nt][3] * s1);
            *reinterpret_cast<float2*>(o0 + co) = v0;
            *reinterpret_cast<float2*>(o1 + co) = v1;
        }
    }
}

// ============================================================================
// Host launcher
// ============================================================================
extern "C" void kernel_launch(void* const* d_in, const int* in_sizes, int n_in,
                              void* d_out, int out_size) {
    const float* x  = (const float*)d_in[0];
    const float* st = (n_in > 1) ? (const float*)d_in[1] : nullptr;
    const float* kr = (n_in > 2) ? (const float*)d_in[2] : nullptr;
    for (int i = 0; i < n_in; ++i) {
        if (in_sizes[i] == BATCH * HH * WWD * CIN) x  = (const float*)d_in[i];
        else if (in_sizes[i] == BATCH * CIN)       st = (const float*)d_in[i];
        else if (in_sizes[i] == 9 * CIN * CO)      kr = (const float*)d_in[i];
    }
    float* out = (float*)d_out;

    cudaFuncSetAttribute(modconv_main, cudaFuncAttributeMaxDynamicSharedMemorySize,
                         (int)SMEM_BYTES);

    prep_wt<<<dim3(8, 8, 9), dim3(32, 8)>>>(kr);
    prep_k2<<<256, 256>>>(kr);
    prep_norm<<<16, 256>>>(st);
    prep_x<<<16384, 256>>>(x, st);
    modconv_main<<<512, 256, SMEM_BYTES>>>(out);
}

// round 6
// speedup vs baseline: 2.3280x; 1.2517x over previous
#include <cuda_runtime.h>
#include <cuda_fp16.h>
#include <cstdint>
#include <cstddef>

// ============================================================================
// ModConv2D on GB300 (sm_103 base target), fp16 mma.sync implicit-GEMM conv.
//
//   y = conv2d_3x3_same(x * s_b[ci], kernel) * invn_b[co]
//   s_b[ci]    = style[b,ci] + 1
//   invn_b[co] = 1/sqrt( sum_{kh,kw,ci} (kernel*s_b)^2 + 1e-8 )
//
// fp16 inputs (same 10-bit mantissa as tf32), fp32 accumulate.
// R5: warp tile 64x64 (2m x 4n), K-chunk 64 ci (36 iters), 4-stage cp.async.
// ============================================================================

constexpr int BATCH = 16, HH = 64, WWD = 64, CIN = 256, CO = 256;

#define DEVINL __device__ __forceinline__

// scratch (allocation-free rule: __device__ globals)
__device__ __half g_Wh[9 * CO * CIN];             // [tap][co][ci], fp16
__device__ __half g_xh[BATCH * HH * WWD * CIN];   // style-scaled x, fp16
__device__ float  g_K2[CIN * CO];                 // sum_tap k^2
__device__ float  g_invn[BATCH * CO];             // demodulation scale

DEVINL uint32_t smem_u32(const void* p) {
    uint32_t a;
    asm("{ .reg .u64 t; cvta.to.shared.u64 t, %1; cvt.u32.u64 %0, t; }"
        : "=r"(a) : "l"(p));
    return a;
}
DEVINL void cp16(uint32_t dst, const void* src, uint32_t sz) {
    asm volatile("cp.async.cg.shared.global [%0], [%1], 16, %2;"
                 :: "r"(dst), "l"(src), "r"(sz) : "memory");
}
DEVINL void cp_commit() { asm volatile("cp.async.commit_group;" ::: "memory"); }
template <int N> DEVINL void cp_wait() {
    asm volatile("cp.async.wait_group %0;" :: "n"(N) : "memory");
}
DEVINL void ldsm4(uint32_t* r, uint32_t addr) {
    asm volatile("ldmatrix.sync.aligned.m8n8.x4.shared.b16 {%0,%1,%2,%3}, [%4];"
                 : "=r"(r[0]), "=r"(r[1]), "=r"(r[2]), "=r"(r[3]) : "r"(addr));
}
// m16n8k16 fp16 MMA (row-major A, col-major B, fp32 accum)
DEVINL void mma16(float* d, const uint32_t* a, uint32_t b0, uint32_t b1) {
    asm volatile(
        "mma.sync.aligned.m16n8k16.row.col.f32.f16.f16.f32 "
        "{%0,%1,%2,%3}, {%4,%5,%6,%7}, {%8,%9}, {%0,%1,%2,%3};"
        : "+f"(d[0]), "+f"(d[1]), "+f"(d[2]), "+f"(d[3])
        : "r"(a[0]), "r"(a[1]), "r"(a[2]), "r"(a[3]), "r"(b0), "r"(b1));
}

// ------------- smem layout -------------
// Stage: A 128 rows x 64 ci half (16KB, 128B rows) + B 256 co x 64 ci (32KB).
// Row swizzle: 16B chunk c (0..7) at byte  r*128 + ((c ^ (r&7))<<4)
// -> conflict-free cp.async stores and ldmatrix reads; ks advance = XOR(ks<<5).
constexpr uint32_t STAGE_BYTES = 49152;
constexpr uint32_t B_OFF       = 16384;
constexpr uint32_t SMEM_BYTES  = 4 * STAGE_BYTES + 1024;

// ============================================================================
// Prolog 1: weights -> g_Wh[tap][co][ci] (transpose + fp16)
// ============================================================================
__global__ void prep_wt(const float* __restrict__ ker) {
    __shared__ float t[32][33];
    const int tap = blockIdx.z, ci0 = blockIdx.y * 32, co0 = blockIdx.x * 32;
    const int tx = threadIdx.x, ty = threadIdx.y;   // (32, 8)
    #pragma unroll
    for (int i = 0; i < 32; i += 8)
        t[ty + i][tx] = ker[((tap * 256) + (ci0 + ty + i)) * 256 + co0 + tx];
    __syncthreads();
    #pragma unroll
    for (int i = 0; i < 32; i += 8)
        g_Wh[((tap * 256) + (co0 + ty + i)) * 256 + ci0 + tx] =
            __float2half_rn(t[tx][ty + i]);
}

// ============================================================================
// Prolog 2a: K2[ci][co] = sum_tap ker^2 (wide, coalesced over co)
// ============================================================================
__global__ void prep_k2(const float* __restrict__ ker) {
    const int ci = blockIdx.x, co = threadIdx.x;
    float a = 0.0f;
    #pragma unroll
    for (int t = 0; t < 9; ++t) {
        float v = ker[((size_t)t * 256 + ci) * 256 + co];
        a = fmaf(v, v, a);
    }
    g_K2[ci * 256 + co] = a;
}

// ============================================================================
// Prolog 2b: invn[b][co] = rsqrt( sum_ci K2[ci][co]*s^2 + 1e-8 )
// ============================================================================
__global__ void prep_norm(const float* __restrict__ style) {
    __shared__ float s2[256];
    const int b = blockIdx.x, co = threadIdx.x;
    float s = style[b * 256 + co] + 1.0f;
    s2[co] = s * s;
    __syncthreads();
    float acc = 0.0f;
    #pragma unroll 8
    for (int ci = 0; ci < 256; ++ci)
        acc = fmaf(g_K2[ci * 256 + co], s2[ci], acc);
    float a = acc + 1e-8f;
    float r = rsqrtf(a);
    r = r * (1.5f - 0.5f * a * r * r);   // Newton step
    g_invn[b * 256 + co] = r;
}

// ============================================================================
// Prolog 3: xh = fp16(x * (style+1)), NHWC layout preserved
// ============================================================================
__global__ void prep_x(const float* __restrict__ x, const float* __restrict__ style) {
    __shared__ float s[256];
    const size_t i = (size_t)blockIdx.x * 256 + threadIdx.x;  // over 4M float4
    const int b = (int)(i >> 18);
    s[threadIdx.x] = style[b * 256 + threadIdx.x] + 1.0f;
    __syncthreads();
    float4 v = reinterpret_cast<const float4*>(x)[i];
    const int ci = ((int)i & 63) * 4;
    __half2 h0 = __floats2half2_rn(v.x * s[ci + 0], v.y * s[ci + 1]);
    __half2 h1 = __floats2half2_rn(v.z * s[ci + 2], v.w * s[ci + 3]);
    uint2 o;
    o.x = *reinterpret_cast<uint32_t*>(&h0);
    o.y = *reinterpret_cast<uint32_t*>(&h1);
    reinterpret_cast<uint2*>(g_xh)[i] = o;
}

// ============================================================================
// Main GEMM: 512 CTAs x 256 thr, CTA tile 128 pixels x 256 cout,
// K = 36 chunks of 64 ci (9 taps x 4). 4-stage cp.async pipeline,
// ldmatrix.x4 + m16n8k16 fp16 mma. Warp tile 64x64 (2m x 4n warps).
// ============================================================================
__global__ void __launch_bounds__(256, 1)
modconv_main(float* __restrict__ out) {
    extern __shared__ char smem[];
    const uint32_t sb = smem_u32(smem);
    const int tid = threadIdx.x, lid = tid & 31, wid = tid >> 5;
    const int g = lid >> 2, tg = lid & 3;
    const int wm = wid & 1, wn = wid >> 1;
    const int M0 = wm * 64, N0 = wn * 64;
    const int tile = blockIdx.x;
    const int b = tile >> 5;             // 32 tiles (of 128 pixels) per sample
    const int h0 = (tile & 31) * 2;      // 2 image rows per tile

    // hoist demod scales into smem now; consumed after final barrier
    float* invn_sm = reinterpret_cast<float*>(smem + 4 * STAGE_BYTES);
    invn_sm[tid] = g_invn[b * 256 + tid];

    float acc[4][8][4];
    #pragma unroll
    for (int mt = 0; mt < 4; ++mt)
        #pragma unroll
        for (int nf = 0; nf < 8; ++nf)
            #pragma unroll
            for (int i = 0; i < 4; ++i) acc[mt][nf][i] = 0.0f;

    // per-lane ldmatrix base offsets (stage-relative, ks=0); ks -> XOR (ks<<5)
    const int la = lid & 7;
    uint32_t offA[4], offB[4];
    {
        const int qa = (lid >> 3) & 1, ha = (lid >> 4) & 1;  // A: row+8 sel, ci-half sel
        #pragma unroll
        for (int mt = 0; mt < 4; ++mt) {
            const int r = M0 + mt * 16 + la + qa * 8;
            offA[mt] = (uint32_t)(r * 128 + ((ha ^ (r & 7)) << 4));
        }
        const int qb = (lid >> 4) & 1, hb = (lid >> 3) & 1;  // B: co+8 sel, ci-half sel
        #pragma unroll
        for (int j4 = 0; j4 < 4; ++j4) {
            const int r = N0 + j4 * 16 + la + qb * 8;
            offB[j4] = B_OFF + (uint32_t)(r * 128 + ((hb ^ (r & 7)) << 4));
        }
    }

    auto load_stage = [&](int slot, int it) {
        const int tap = it >> 2, ci0 = (it & 3) * 64;
        const int dh = tap / 3 - 1, dw = tap % 3 - 1;
        const uint32_t abase = sb + (uint32_t)slot * STAGE_BYTES;
        const uint32_t bbase = abase + B_OFF;
        // A: 128 rows x 8 chunks of 16B = 1024 chunks, 4/thread
        #pragma unroll
        for (int j = 0; j < 4; ++j) {
            const int q = tid + j * 256;
            const int m = q >> 3, c = q & 7;
            const int h = h0 + (m >> 6) + dh;
            const int w = (m & 63) + dw;
            const bool ok = ((unsigned)h < 64u) & ((unsigned)w < 64u);
            const __half* src = ok
                ? g_xh + (((size_t)((b * 64 + h) * 64 + w)) * 256 + ci0 + c * 8)
                : g_xh;
            cp16(abase + (uint32_t)(m * 128 + ((c ^ (m & 7)) << 4)),
                 src, ok ? 16u : 0u);
        }
        // B: 256 co x 8 chunks = 2048 chunks, 8/thread
        #pragma unroll
        for (int j = 0; j < 8; ++j) {
            const int q = tid + j * 256;
            const int co = q >> 3, c = q & 7;
            const __half* src = g_Wh + ((size_t)(tap * 256 + co) * 256 + ci0 + c * 8);
            cp16(bbase + (uint32_t)(co * 128 + ((c ^ (co & 7)) << 4)), src, 16u);
        }
    };

    load_stage(0, 0); cp_commit();
    load_stage(1, 1); cp_commit();
    load_stage(2, 2); cp_commit();

    #pragma unroll 1
    for (int it = 0; it < 36; ++it) {
        cp_wait<2>();
        __syncthreads();
        if (it + 3 < 36) load_stage((it + 3) & 3, it + 3);
        cp_commit();

        const uint32_t stb = sb + (uint32_t)(it & 3) * STAGE_BYTES;
        #pragma unroll
        for (int ks = 0; ks < 4; ++ks) {
            const uint32_t kx = (uint32_t)ks << 5;
            uint32_t a[4][4];
            #pragma unroll
            for (int mt = 0; mt < 4; ++mt)
                ldsm4(a[mt], stb + (offA[mt] ^ kx));
            #pragma unroll
            for (int j4 = 0; j4 < 4; ++j4) {
                uint32_t bf[4];
                ldsm4(bf, stb + (offB[j4] ^ kx));
                #pragma unroll
                for (int mt = 0; mt < 4; ++mt) {
                    mma16(acc[mt][2 * j4],     a[mt], bf[0], bf[1]);
                    mma16(acc[mt][2 * j4 + 1], a[mt], bf[2], bf[3]);
                }
            }
        }
    }

    // ---- epilogue: demodulate + store ----
    __syncthreads();   // invn_sm visible (written pre-loop)

    #pragma unroll
    for (int mt = 0; mt < 4; ++mt) {
        const int m = tile * 128 + M0 + mt * 16 + g;
        float* o0 = out + (size_t)m * 256;
        float* o1 = out + (size_t)(m + 8) * 256;
        #pragma unroll
        for (int nf = 0; nf < 8; ++nf) {
            const int co = N0 + nf * 8 + tg * 2;
            const float s0 = invn_sm[co], s1 = invn_sm[co + 1];
            float2 v0 = make_float2(acc[mt][nf][0] * s0, acc[mt][nf][1] * s1);
            float2 v1 = make_float2(acc[mt][nf][2] * s0, acc[mt][nf][3] * s1);
            *reinterpret_cast<float2*>(o0 + co) = v0;
            *reinterpret_cast<float2*>(o1 + co) = v1;
        }
    }
}

// ============================================================================
// Host launcher
// ============================================================================
extern "C" void kernel_launch(void* const* d_in, const int* in_sizes, int n_in,
                              void* d_out, int out_size) {
    const float* x  = (const float*)d_in[0];
    const float* st = (n_in > 1) ? (const float*)d_in[1] : nullptr;
    const float* kr = (n_in > 2) ? (const float*)d_in[2] : nullptr;
    for (int i = 0; i < n_in; ++i) {
        if (in_sizes[i] == BATCH * HH * WWD * CIN) x  = (const float*)d_in[i];
        else if (in_sizes[i] == BATCH * CIN)       st = (const float*)d_in[i];
        else if (in_sizes[i] == 9 * CIN * CO)      kr = (const float*)d_in[i];
    }
    float* out = (float*)d_out;

    cudaFuncSetAttribute(modconv_main, cudaFuncAttributeMaxDynamicSharedMemorySize,
                         (int)SMEM_BYTES);

    prep_wt<<<dim3(8, 8, 9), dim3(32, 8)>>>(kr);
    prep_k2<<<256, 256>>>(kr);
    prep_norm<<<16, 256>>>(st);
    prep_x<<<16384, 256>>>(x, st);
    modconv_main<<<512, 256, SMEM_BYTES>>>(out);
}

// round 7
// speedup vs baseline: 2.3918x; 1.0274x over previous
#include <cuda_runtime.h>
#include <cuda_fp16.h>
#include <cstdint>
#include <cstddef>

// ============================================================================
// ModConv2D on GB300 (sm_103 base target), fp16 mma.sync implicit-GEMM conv.
//
//   y = conv2d_3x3_same(x * s_b[ci], kernel) * invn_b[co]
//   s_b[ci]    = style[b,ci] + 1
//   invn_b[co] = 1/sqrt( sum_{kh,kw,ci} (kernel*s_b)^2 + 1e-8 )
//
// R7: 2 CTAs/SM. CTA = 128 thr, tile 128 pixels x 128 cout, warp tile 64x64,
// K = 36 chunks of 64 ci, 3-stage cp.async pipeline (32KB/stage).
// ============================================================================

constexpr int BATCH = 16, HH = 64, WWD = 64, CIN = 256, CO = 256;

#define DEVINL __device__ __forceinline__

// scratch (allocation-free rule: __device__ globals)
__device__ __half g_Wh[9 * CO * CIN];             // [tap][co][ci], fp16
__device__ __half g_xh[BATCH * HH * WWD * CIN];   // style-scaled x, fp16
__device__ float  g_K2[CIN * CO];                 // sum_tap k^2
__device__ float  g_invn[BATCH * CO];             // demodulation scale

DEVINL uint32_t smem_u32(const void* p) {
    uint32_t a;
    asm("{ .reg .u64 t; cvta.to.shared.u64 t, %1; cvt.u32.u64 %0, t; }"
        : "=r"(a) : "l"(p));
    return a;
}
DEVINL void cp16(uint32_t dst, const void* src, uint32_t sz) {
    asm volatile("cp.async.cg.shared.global [%0], [%1], 16, %2;"
                 :: "r"(dst), "l"(src), "r"(sz) : "memory");
}
DEVINL void cp_commit() { asm volatile("cp.async.commit_group;" ::: "memory"); }
template <int N> DEVINL void cp_wait() {
    asm volatile("cp.async.wait_group %0;" :: "n"(N) : "memory");
}
DEVINL void ldsm4(uint32_t* r, uint32_t addr) {
    asm volatile("ldmatrix.sync.aligned.m8n8.x4.shared.b16 {%0,%1,%2,%3}, [%4];"
                 : "=r"(r[0]), "=r"(r[1]), "=r"(r[2]), "=r"(r[3]) : "r"(addr));
}
// m16n8k16 fp16 MMA (row-major A, col-major B, fp32 accum)
DEVINL void mma16(float* d, const uint32_t* a, uint32_t b0, uint32_t b1) {
    asm volatile(
        "mma.sync.aligned.m16n8k16.row.col.f32.f16.f16.f32 "
        "{%0,%1,%2,%3}, {%4,%5,%6,%7}, {%8,%9}, {%0,%1,%2,%3};"
        : "+f"(d[0]), "+f"(d[1]), "+f"(d[2]), "+f"(d[3])
        : "r"(a[0]), "r"(a[1]), "r"(a[2]), "r"(a[3]), "r"(b0), "r"(b1));
}

// ------------- smem layout -------------
// Stage: A 128 rows x 64 ci (16KB, 128B rows) + B 128 co x 64 ci (16KB).
// Row swizzle: 16B chunk c (0..7) at byte r*128 + ((c ^ (r&7))<<4)
// -> conflict-free cp.async stores and ldmatrix reads; ks advance = XOR(ks<<5).
constexpr uint32_t STAGE_BYTES = 32768;
constexpr uint32_t B_OFF       = 16384;
constexpr uint32_t SMEM_BYTES  = 3 * STAGE_BYTES + 512;

// ============================================================================
// Prolog 1: weights -> g_Wh[tap][co][ci] (transpose + fp16)
// ============================================================================
__global__ void prep_wt(const float* __restrict__ ker) {
    __shared__ float t[32][33];
    const int tap = blockIdx.z, ci0 = blockIdx.y * 32, co0 = blockIdx.x * 32;
    const int tx = threadIdx.x, ty = threadIdx.y;   // (32, 8)
    #pragma unroll
    for (int i = 0; i < 32; i += 8)
        t[ty + i][tx] = ker[((tap * 256) + (ci0 + ty + i)) * 256 + co0 + tx];
    __syncthreads();
    #pragma unroll
    for (int i = 0; i < 32; i += 8)
        g_Wh[((tap * 256) + (co0 + ty + i)) * 256 + ci0 + tx] =
            __float2half_rn(t[tx][ty + i]);
}

// ============================================================================
// Prolog 2a: K2[ci][co] = sum_tap ker^2 (wide, coalesced over co)
// ============================================================================
__global__ void prep_k2(const float* __restrict__ ker) {
    const int ci = blockIdx.x, co = threadIdx.x;
    float a = 0.0f;
    #pragma unroll
    for (int t = 0; t < 9; ++t) {
        float v = ker[((size_t)t * 256 + ci) * 256 + co];
        a = fmaf(v, v, a);
    }
    g_K2[ci * 256 + co] = a;
}

// ============================================================================
// Prolog 2b: invn[b][co] = rsqrt( sum_ci K2[ci][co]*s^2 + 1e-8 )
// ============================================================================
__global__ void prep_norm(const float* __restrict__ style) {
    __shared__ float s2[256];
    const int b = blockIdx.x, co = threadIdx.x;
    float s = style[b * 256 + co] + 1.0f;
    s2[co] = s * s;
    __syncthreads();
    float acc = 0.0f;
    #pragma unroll 8
    for (int ci = 0; ci < 256; ++ci)
        acc = fmaf(g_K2[ci * 256 + co], s2[ci], acc);
    float a = acc + 1e-8f;
    float r = rsqrtf(a);
    r = r * (1.5f - 0.5f * a * r * r);   // Newton step
    g_invn[b * 256 + co] = r;
}

// ============================================================================
// Prolog 3: xh = fp16(x * (style+1)). 4 float4/thread, block-strided so each
// inner load is fully coalesced; per-thread style float4 loaded once (ci
// phase is invariant across the 4 strided elements). No smem, no barrier.
// ============================================================================
__global__ void prep_x(const float* __restrict__ x, const float* __restrict__ style) {
    const size_t base = (size_t)blockIdx.x * 1024 + threadIdx.x;  // float4 index
    const int b = (int)(base >> 18);                  // 1024-aligned blocks: const
    const int ci = ((int)base & 63) * 4;              // same for all 4 k-steps
    const float4 s4 = __ldg(reinterpret_cast<const float4*>(style + b * 256 + ci));
    const float sx = s4.x + 1.0f, sy = s4.y + 1.0f;
    const float sz = s4.z + 1.0f, sw = s4.w + 1.0f;
    #pragma unroll
    for (int k = 0; k < 4; ++k) {
        const size_t i = base + (size_t)k * 256;
        float4 v = __ldg(reinterpret_cast<const float4*>(x) + i);
        __half2 h0 = __floats2half2_rn(v.x * sx, v.y * sy);
        __half2 h1 = __floats2half2_rn(v.z * sz, v.w * sw);
        uint2 o;
        o.x = *reinterpret_cast<uint32_t*>(&h0);
        o.y = *reinterpret_cast<uint32_t*>(&h1);
        reinterpret_cast<uint2*>(g_xh)[i] = o;
    }
}

// ============================================================================
// Main GEMM: 1024 CTAs x 128 thr (2 CTAs/SM), CTA tile 128 pixels x 128 cout,
// K = 36 chunks of 64 ci. 3-stage cp.async pipeline, ldmatrix.x4 +
// m16n8k16 fp16 mma. Warp tile 64x64 (2m x 2n warps).
// ============================================================================
__global__ void __launch_bounds__(128, 2)
modconv_main(float* __restrict__ out) {
    extern __shared__ char smem[];
    const uint32_t sb = smem_u32(smem);
    const int tid = threadIdx.x, lid = tid & 31, wid = tid >> 5;
    const int g = lid >> 2, tg = lid & 3;
    const int wm = wid & 1, wn = wid >> 1;
    const int M0 = wm * 64, N0 = wn * 64;
    const int tile = blockIdx.x;
    const int pt = tile >> 1;            // pixel tile 0..511
    const int ch = tile & 1;             // cout half (0: co 0..127, 1: 128..255)
    const int b = pt >> 5;               // 32 pixel-tiles per sample
    const int h0 = (pt & 31) * 2;        // 2 image rows per tile

    // hoist demod scales (this CTA's 128 cout) into smem; used after final sync
    float* invn_sm = reinterpret_cast<float*>(smem + 3 * STAGE_BYTES);
    invn_sm[tid] = g_invn[b * 256 + ch * 128 + tid];

    float acc[4][8][4];
    #pragma unroll
    for (int mt = 0; mt < 4; ++mt)
        #pragma unroll
        for (int nf = 0; nf < 8; ++nf)
            #pragma unroll
            for (int i = 0; i < 4; ++i) acc[mt][nf][i] = 0.0f;

    // per-lane ldmatrix base offsets (stage-relative, ks=0); ks -> XOR (ks<<5)
    const int la = lid & 7;
    uint32_t offA[4], offB[4];
    {
        const int qa = (lid >> 3) & 1, ha = (lid >> 4) & 1;
        #pragma unroll
        for (int mt = 0; mt < 4; ++mt) {
            const int r = M0 + mt * 16 + la + qa * 8;
            offA[mt] = (uint32_t)(r * 128 + ((ha ^ (r & 7)) << 4));
        }
        const int qb = (lid >> 4) & 1, hb = (lid >> 3) & 1;
        #pragma unroll
        for (int j4 = 0; j4 < 4; ++j4) {
            const int r = N0 + j4 * 16 + la + qb * 8;
            offB[j4] = B_OFF + (uint32_t)(r * 128 + ((hb ^ (r & 7)) << 4));
        }
    }

    auto load_stage = [&](int slot, int it) {
        const int tap = it >> 2, ci0 = (it & 3) * 64;
        const int dh = tap / 3 - 1, dw = tap % 3 - 1;
        const uint32_t abase = sb + (uint32_t)slot * STAGE_BYTES;
        const uint32_t bbase = abase + B_OFF;
        // A: 128 rows x 8 chunks of 16B = 1024 chunks, 8/thread
        #pragma unroll
        for (int j = 0; j < 8; ++j) {
            const int q = tid + j * 128;
            const int m = q >> 3, c = q & 7;
            const int h = h0 + (m >> 6) + dh;
            const int w = (m & 63) + dw;
            const bool ok = ((unsigned)h < 64u) & ((unsigned)w < 64u);
            const __half* src = ok
                ? g_xh + (((size_t)((b * 64 + h) * 64 + w)) * 256 + ci0 + c * 8)
                : g_xh;
            cp16(abase + (uint32_t)(m * 128 + ((c ^ (m & 7)) << 4)),
                 src, ok ? 16u : 0u);
        }
        // B: 128 co x 8 chunks = 1024 chunks, 8/thread
        #pragma unroll
        for (int j = 0; j < 8; ++j) {
            const int q = tid + j * 128;
            const int co = q >> 3, c = q & 7;
            const __half* src =
                g_Wh + ((size_t)(tap * 256 + ch * 128 + co) * 256 + ci0 + c * 8);
            cp16(bbase + (uint32_t)(co * 128 + ((c ^ (co & 7)) << 4)), src, 16u);
        }
    };

    load_stage(0, 0); cp_commit();
    load_stage(1, 1); cp_commit();

    #pragma unroll 1
    for (int it = 0; it < 36; ++it) {
        cp_wait<1>();
        __syncthreads();
        if (it + 2 < 36) load_stage((it + 2) % 3, it + 2);
        cp_commit();

        const uint32_t stb = sb + (uint32_t)(it % 3) * STAGE_BYTES;
        #pragma unroll
        for (int ks = 0; ks < 4; ++ks) {
            const uint32_t kx = (uint32_t)ks << 5;
            uint32_t a[4][4];
            #pragma unroll
            for (int mt = 0; mt < 4; ++mt)
                ldsm4(a[mt], stb + (offA[mt] ^ kx));
            #pragma unroll
            for (int j4 = 0; j4 < 4; ++j4) {
                uint32_t bf[4];
                ldsm4(bf, stb + (offB[j4] ^ kx));
                #pragma unroll
                for (int mt = 0; mt < 4; ++mt) {
                    mma16(acc[mt][2 * j4],     a[mt], bf[0], bf[1]);
                    mma16(acc[mt][2 * j4 + 1], a[mt], bf[2], bf[3]);
                }
            }
        }
    }

    // ---- epilogue: demodulate + store ----
    __syncthreads();   // invn_sm visible (written pre-loop)

    #pragma unroll
    for (int mt = 0; mt < 4; ++mt) {
        const int m = pt * 128 + M0 + mt * 16 + g;
        float* o0 = out + (size_t)m * 256 + ch * 128;
        float* o1 = out + (size_t)(m + 8) * 256 + ch * 128;
        #pragma unroll
        for (int nf = 0; nf < 8; ++nf) {
            const int co = N0 + nf * 8 + tg * 2;
            const float s0 = invn_sm[co], s1 = invn_sm[co + 1];
            float2 v0 = make_float2(acc[mt][nf][0] * s0, acc[mt][nf][1] * s1);
            float2 v1 = make_float2(acc[mt][nf][2] * s0, acc[mt][nf][3] * s1);
            *reinterpret_cast<float2*>(o0 + co) = v0;
            *reinterpret_cast<float2*>(o1 + co) = v1;
        }
    }
}

// ============================================================================
// Host launcher
// ============================================================================
extern "C" void kernel_launch(void* const* d_in, const int* in_sizes, int n_in,
                              void* d_out, int out_size) {
    const float* x  = (const float*)d_in[0];
    const float* st = (n_in > 1) ? (const float*)d_in[1] : nullptr;
    const float* kr = (n_in > 2) ? (const float*)d_in[2] : nullptr;
    for (int i = 0; i < n_in; ++i) {
        if (in_sizes[i] == BATCH * HH * WWD * CIN) x  = (const float*)d_in[i];
        else if (in_sizes[i] == BATCH * CIN)       st = (const float*)d_in[i];
        else if (in_sizes[i] == 9 * CIN * CO)      kr = (const float*)d_in[i];
    }
    float* out = (float*)d_out;

    cudaFuncSetAttribute(modconv_main, cudaFuncAttributeMaxDynamicSharedMemorySize,
                         (int)SMEM_BYTES);

    prep_wt<<<dim3(8, 8, 9), dim3(32, 8)>>>(kr);
    prep_k2<<<256, 256>>>(kr);
    prep_norm<<<16, 256>>>(st);
    prep_x<<<4096, 256>>>(x, st);
    modconv_main<<<1024, 128, SMEM_BYTES>>>(out);
}